// round 15
// baseline (speedup 1.0000x reference)
#include <cuda_runtime.h>
#include <cuda_bf16.h>
#include <float.h>
#include <math.h>

#define NUM_CLASSES 13
#define C1 (NUM_CLASSES + 1)   // 14
#define Bn 64
#define Qn 900
#define Tn 128
#define NTC 128                // cost kernel threads
#define NT 256
#define NTH 256                // hungarian threads (8 warps)
#define NWARP (NTH / 32)
#define JPT 4                  // columns per thread (float4)
#define NACT (Qn / JPT)        // 225 active scan threads
#define TSPLIT 2
#define TCH (Tn / TSPLIT)      // 64 targets per cost CTA

// ---- scratch (static device globals; no allocation allowed) ----
__device__ __align__(256) float g_cost[Bn * Tn * Qn];   // cost[b][t][q]
__device__ float  g_lse[Bn * Qn];         // logsumexp per (b,q)
__device__ float  g_rowu[Bn * Tn];        // row minima (exact matrix entries)
__device__ int    g_rowarg[Bn * Tn];      // argmin col (1-based)
__device__ double g_partial[Bn];          // per-image loss
__device__ int    g_ctr = 0;              // completion counter (reset each run)

// order-preserving float <-> uint32 (no NaNs in costs)
__device__ __forceinline__ unsigned enc_f(float f) {
    unsigned u = __float_as_uint(f);
    return (u & 0x80000000u) ? ~u : (u | 0x80000000u);
}
__device__ __forceinline__ float dec_f(unsigned e) {
    unsigned x = (e & 0x80000000u) ? (e & 0x7fffffffu) : ~e;
    return __uint_as_float(x);
}

// ============================================================================
// 1) Cost matrix (R6-proven math; 128-thread CTAs for 2x grid occupancy)
// ============================================================================
__global__ __launch_bounds__(NTC) void cost_kernel(
    const float* __restrict__ pc, const float* __restrict__ pb,
    const int* __restrict__ lab, const float* __restrict__ tb)
{
    int b    = blockIdx.y;
    int tseg = blockIdx.z;
    int t0   = tseg * TCH;
    int tid  = threadIdx.x;
    int q    = blockIdx.x * NTC + tid;

    __shared__ float4 s_tb4[TCH];
    __shared__ int    s_lab[TCH];
    __shared__ float  s_negp[C1][NTC];

    for (int i = tid; i < TCH; i += NTC) {
        s_tb4[i] = reinterpret_cast<const float4*>(tb)[b * Tn + t0 + i];
        s_lab[i] = lab[b * Tn + t0 + i];
    }

    float4 pbq = make_float4(0.f, 0.f, 0.f, 0.f);
    if (q < Qn) {
        const float* lg = pc + (size_t)(b * Qn + q) * C1;
        float m = lg[0];
        #pragma unroll
        for (int c = 1; c < C1; c++) m = fmaxf(m, lg[c]);
        float e[C1]; float se = 0.f;
        #pragma unroll
        for (int c = 0; c < C1; c++) { e[c] = __expf(lg[c] - m); se += e[c]; }
        float inv = 1.0f / se;
        #pragma unroll
        for (int c = 0; c < C1; c++) s_negp[c][tid] = -e[c] * inv;
        if (tseg == 0) g_lse[b * Qn + q] = m + logf(se);
        pbq = *reinterpret_cast<const float4*>(pb + (size_t)(b * Qn + q) * 4);
    }
    __syncthreads();
    if (q >= Qn) return;

    float* crow = g_cost + (size_t)b * Tn * Qn + (size_t)t0 * Qn + q;
    #pragma unroll 8
    for (int t = 0; t < TCH; t++) {
        float4 tb4 = s_tb4[t];
        float cc = s_negp[s_lab[t]][tid];
        float cb = fabsf(pbq.x - tb4.x) + fabsf(pbq.y - tb4.y)
                 + fabsf(pbq.z - tb4.z) + fabsf(pbq.w - tb4.w);
        crow[(size_t)t * Qn] = cb + cc;
    }
}

// ============================================================================
// 1b) Row minima of RAW costs: one warp per (image,row).
//     u[i] = exact matrix entry -> argmin edge reduced cost exactly 0 (sound).
// ============================================================================
__global__ __launch_bounds__(NT) void rowmin_kernel()
{
    int lane = threadIdx.x & 31;
    int widx = blockIdx.x * (NT / 32) + (threadIdx.x >> 5);   // global row id
    if (widx >= Bn * Tn) return;
    const float* crow = g_cost + (size_t)widx * Qn;

    unsigned long long best = ~0ull;
    #pragma unroll
    for (int s = 0; s < 8; s++) {
        if (s == 7 && lane != 0) break;
        int j0 = (s < 7) ? (s * 128 + lane * 4) : 896;
        float4 c4 = __ldg(reinterpret_cast<const float4*>(crow + j0));
        #pragma unroll
        for (int k = 0; k < 4; k++) {
            unsigned long long e =
                ((unsigned long long)enc_f((&c4.x)[k]) << 32) | (unsigned)(j0 + k + 1);
            if (e < best) best = e;
        }
    }
    #pragma unroll
    for (int s = 16; s; s >>= 1) {
        unsigned long long o = __shfl_down_sync(0xffffffffu, best, s);
        if (o < best) best = o;
    }
    if (lane == 0) {
        g_rowu[widx]   = dec_f((unsigned)(best >> 32));
        g_rowarg[widx] = (int)(best & 0xffffffffu);
    }
}

// ============================================================================
// 2) Hungarian (R14-proven) with (enc | j1 | next-row) packed atomic slot:
//    leaders pre-read p[cand] before the barrier, so after the barrier one
//    LDS.64 yields value+column+row and the winner-row LDG issues immediately.
//    Fused loss + finalize.
// ============================================================================
__global__ __launch_bounds__(NTH) void hungarian_loss_kernel(
    const float* __restrict__ pc, const float* __restrict__ pb,
    const int* __restrict__ lab, const float* __restrict__ tb,
    float* __restrict__ out)
{
    int b = blockIdx.x;
    int tid = threadIdx.x;
    int lane = tid & 31;

    __shared__ float u[Tn + 1];
    __shared__ int   way[Qn + 1];
    __shared__ int   p[Qn + 1];
    __shared__ int   rowq[Tn + 1];
    __shared__ unsigned char s_assigned[Tn + 1];
    __shared__ unsigned long long s_gmin[2];   // parity double-buffered argmin
    __shared__ double   sred[NTH];
    __shared__ int      s_last;

    for (int j = tid; j <= Qn; j += NTH) p[j] = 0;
    for (int i = tid; i < Tn; i += NTH) {
        u[i + 1]    = g_rowu[b * Tn + i];
        rowq[i + 1] = g_rowarg[b * Tn + i];
    }
    if (tid == 0) { s_gmin[0] = ~0ull; s_gmin[1] = ~0ull; }
    __syncthreads();

    const float* cost = g_cost + (size_t)b * Tn * Qn;
    const bool valid = (tid < NACT);
    const int  jbase = JPT * tid + 1;     // first owned column (1-based)

    // per-thread column state (owner-private)
    float v4[JPT], minv4[JPT], tu4[JPT];
    unsigned mask = 0;
    #pragma unroll
    for (int k = 0; k < JPT; k++) { v4[k] = 0.f; minv4[k] = FLT_MAX; }

    // ---- greedy assignment (serial, trivial) ----
    if (tid == 0) {
        for (int i = 1; i <= Tn; i++) {
            int j = rowq[i];
            if (p[j] == 0) { p[j] = i; s_assigned[i] = 1; }
            else s_assigned[i] = 0;
        }
    }
    __syncthreads();

    // ---- Dijkstra phases for free rows (deferred duals, register state) ----
    for (int i = 1; i <= Tn; i++) {
        if (s_assigned[i]) continue;
        if (tid == 0) p[0] = i;

        int   i0 = i;
        float C  = 0.f;
        int   lastj1 = 0;
        int   it = 0;
        int   jfinal; float Cf;

        while (true) {
            int par = it & 1;
            float4 cr = make_float4(0.f, 0.f, 0.f, 0.f);
            if (valid) cr = __ldg(reinterpret_cast<const float4*>(
                                  cost + (size_t)(i0 - 1) * Qn + (jbase - 1)));
            float aC = u[i0] - C;

            unsigned benc = 0xFFFFFFFFu; int bj = 0x7FFFFFFF;
            if (valid) {
                #pragma unroll
                for (int k = 0; k < JPT; k++) {
                    if (!(mask & (1u << k))) {
                        float r = (&cr.x)[k] - aC - v4[k];
                        if (r < minv4[k]) { minv4[k] = r; way[jbase + k] = lastj1; }
                        unsigned e = enc_f(minv4[k]);
                        if (e < benc) { benc = e; bj = jbase + k; }
                    }
                }
            }
            unsigned m = __reduce_min_sync(0xffffffffu, benc);
            int cand = (benc == m) ? bj : 0x7FFFFFFF;
            int jm = __reduce_min_sync(0xffffffffu, cand);
            // pack (enc:32 | j1:10 | nextrow:8); ordering = (enc, j1) since
            // j1 is unique per warp -> i0n low bits never decide the min.
            if (lane == 0 && jm != 0x7FFFFFFF) {
                int inext = p[jm];            // pre-barrier read; p stable in-phase
                atomicMin(&s_gmin[par],
                          ((unsigned long long)m << 18)
                        | ((unsigned long long)(unsigned)jm << 8)
                        | (unsigned long long)(unsigned)inext);
            }
            if (tid == 0) s_gmin[par ^ 1] = ~0ull;   // reset next buffer
            __syncthreads();

            unsigned long long g = s_gmin[par];
            unsigned ge = (unsigned)(g >> 18);
            int j1  = (int)((g >> 8) & 0x3FFull);
            int i0n = (int)(g & 0xFFull);
            float Cn = dec_f(ge);
            if (i0n == 0) { jfinal = j1; Cf = Cn; break; }
            unsigned k1 = (unsigned)(j1 - jbase);
            if (valid && k1 < JPT) { mask |= 1u << k1; tu4[k1] = Cn; }
            lastj1 = j1; C = Cn; i0 = i0n; it++;
        }

        // apply duals (distinct rows per column => race-free) + reset state
        #pragma unroll
        for (int k = 0; k < JPT; k++) {
            if (mask & (1u << k)) {
                float dv = Cf - tu4[k];
                v4[k] -= dv;
                u[p[jbase + k]] += dv;
            }
            minv4[k] = FLT_MAX;
        }
        mask = 0;
        if (tid == 0) { u[i] += Cf; s_gmin[0] = ~0ull; }  // clean buf0 for next phase
        __syncthreads();
        if (tid == 0) {                      // augment along alternating path
            int j0 = jfinal;
            while (j0) { int jp = way[j0]; p[j0] = p[jp]; j0 = jp; }
            s_assigned[i] = 1;
        }
        __syncthreads();
    }

    // ---- build qi per target in shared ----
    for (int j = tid + 1; j <= Qn; j += NTH) {
        int pi = p[j];
        if (pi > 0) rowq[pi] = j - 1;
    }
    __syncthreads();

    // ================= fused per-image loss =================
    int* tcl = way;
    double l1 = 0.0, gsum = 0.0;
    if (tid < Tn) {
        int t = tid;
        int qi = rowq[t + 1];
        const float4 P = *reinterpret_cast<const float4*>(pb + (size_t)(b * Qn + qi) * 4);
        const float4 G = *reinterpret_cast<const float4*>(tb + (size_t)(b * Tn + t) * 4);
        double px = P.x, py = P.y, pw = P.z, ph = P.w;
        double gx = G.x, gy = G.y, gw = G.z, gh = G.w;
        l1 = fabs(px - gx) + fabs(py - gy) + fabs(pw - gw) + fabs(ph - gh);

        double p0 = px - 0.5 * pw, p1 = py - 0.5 * ph, p2 = px + 0.5 * pw, p3 = py + 0.5 * ph;
        double g0 = gx - 0.5 * gw, g1 = gy - 0.5 * gh, g2 = gx + 0.5 * gw, g3 = gy + 0.5 * gh;
        double a1 = (p2 - p0) * (p3 - p1);
        double a2 = (g2 - g0) * (g3 - g1);
        double iw = fmin(p2, g2) - fmax(p0, g0); iw = iw > 0.0 ? iw : 0.0;
        double ih = fmin(p3, g3) - fmax(p1, g1); ih = ih > 0.0 ? ih : 0.0;
        double inter = iw * ih;
        double uni = a1 + a2 - inter;
        double iou = inter / uni;
        double cw = fmax(p2, g2) - fmin(p0, g0);
        double ch = fmax(p3, g3) - fmin(p1, g1);
        double ac = cw * ch;
        double giou = iou - (ac - uni) / ac;
        gsum = 1.0 - giou;
    }

    for (int q = tid; q < Qn; q += NTH) tcl[q] = NUM_CLASSES;
    __syncthreads();
    if (tid < Tn) tcl[rowq[tid + 1]] = lab[b * Tn + tid];
    __syncthreads();

    double wn = 0.0, ws = 0.0;
    for (int q = tid; q < Qn; q += NTH) {
        int c = tcl[q];
        double w = (c == NUM_CLASSES) ? 0.05 : 1.0;
        double nll = (double)g_lse[b * Qn + q] - (double)pc[(size_t)(b * Qn + q) * C1 + c];
        wn += w * nll; ws += w;
    }

    sred[tid] = l1;   __syncthreads();
    for (int s = NTH / 2; s; s >>= 1) { if (tid < s) sred[tid] += sred[tid + s]; __syncthreads(); }
    double l1t = sred[0]; __syncthreads();
    sred[tid] = gsum; __syncthreads();
    for (int s = NTH / 2; s; s >>= 1) { if (tid < s) sred[tid] += sred[tid + s]; __syncthreads(); }
    double gst = sred[0]; __syncthreads();
    sred[tid] = wn;   __syncthreads();
    for (int s = NTH / 2; s; s >>= 1) { if (tid < s) sred[tid] += sred[tid + s]; __syncthreads(); }
    double wnt = sred[0]; __syncthreads();
    sred[tid] = ws;   __syncthreads();
    for (int s = NTH / 2; s; s >>= 1) { if (tid < s) sred[tid] += sred[tid + s]; __syncthreads(); }
    double wst = sred[0]; __syncthreads();

    if (tid == 0) {
        double bbox = 5.0 * (l1t / (Tn * 4.0)) + 2.0 * (gst / Tn);
        g_partial[b] = bbox + wnt / wst;
        __threadfence();
        int t = atomicAdd(&g_ctr, 1);
        s_last = (t == Bn - 1);
    }
    __syncthreads();

    if (s_last) {
        double val = (tid < Bn) ? ((volatile double*)g_partial)[tid] : 0.0;
        sred[tid] = val; __syncthreads();
        for (int s = NTH / 2; s; s >>= 1) { if (tid < s) sred[tid] += sred[tid + s]; __syncthreads(); }
        if (tid == 0) {
            out[0] = (float)(sred[0] / (double)(Bn * Tn));
            g_ctr = 0;                      // restore for next graph replay
        }
    }
}

extern "C" void kernel_launch(void* const* d_in, const int* in_sizes, int n_in,
                              void* d_out, int out_size)
{
    const float* pc  = (const float*)d_in[0];   // predicted_class [64,900,14]
    const float* pb  = (const float*)d_in[1];   // predicted_bbox  [64,900,4]
    const int*   lab = (const int*)  d_in[2];   // target_labels   [64,128]
    const float* tb  = (const float*)d_in[3];   // target_boxes    [64,128,4]
    float* out = (float*)d_out;

    dim3 cgrid((Qn + NTC - 1) / NTC, Bn, TSPLIT);
    cost_kernel<<<cgrid, NTC>>>(pc, pb, lab, tb);
    rowmin_kernel<<<(Bn * Tn + 7) / 8, NT>>>();
    hungarian_loss_kernel<<<Bn, NTH>>>(pc, pb, lab, tb, out);
}

// round 16
// speedup vs baseline: 1.0180x; 1.0180x over previous
#include <cuda_runtime.h>
#include <cuda_bf16.h>
#include <float.h>
#include <math.h>

#define NUM_CLASSES 13
#define C1 (NUM_CLASSES + 1)   // 14
#define Bn 64
#define Qn 900
#define Tn 128
#define NTC 128                // cost kernel threads
#define NT 256
#define NTH 256                // hungarian threads (8 warps)
#define NWARP (NTH / 32)
#define JPT 4                  // columns per thread (float4)
#define NACT (Qn / JPT)        // 225 active scan threads
#define TSPLIT 2
#define TCH (Tn / TSPLIT)      // 64 targets per cost CTA

// ---- scratch (static device globals; no allocation allowed) ----
__device__ __align__(256) float g_cost[Bn * Tn * Qn];   // cost[b][t][q]
__device__ float  g_lse[Bn * Qn];         // logsumexp per (b,q)
__device__ float  g_rowu[Bn * Tn];        // row minima (exact matrix entries)
__device__ int    g_rowarg[Bn * Tn];      // argmin col (1-based)
__device__ double g_partial[Bn];          // per-image loss
__device__ int    g_ctr = 0;              // completion counter (reset each run)

// order-preserving float <-> uint32 (no NaNs in costs)
__device__ __forceinline__ unsigned enc_f(float f) {
    unsigned u = __float_as_uint(f);
    return (u & 0x80000000u) ? ~u : (u | 0x80000000u);
}
__device__ __forceinline__ float dec_f(unsigned e) {
    unsigned x = (e & 0x80000000u) ? (e & 0x7fffffffu) : ~e;
    return __uint_as_float(x);
}

// ============================================================================
// 1) Cost matrix (R15-measured best: 128-thread CTAs, 1024 blocks)
// ============================================================================
__global__ __launch_bounds__(NTC) void cost_kernel(
    const float* __restrict__ pc, const float* __restrict__ pb,
    const int* __restrict__ lab, const float* __restrict__ tb)
{
    int b    = blockIdx.y;
    int tseg = blockIdx.z;
    int t0   = tseg * TCH;
    int tid  = threadIdx.x;
    int q    = blockIdx.x * NTC + tid;

    __shared__ float4 s_tb4[TCH];
    __shared__ int    s_lab[TCH];
    __shared__ float  s_negp[C1][NTC];

    for (int i = tid; i < TCH; i += NTC) {
        s_tb4[i] = reinterpret_cast<const float4*>(tb)[b * Tn + t0 + i];
        s_lab[i] = lab[b * Tn + t0 + i];
    }

    float4 pbq = make_float4(0.f, 0.f, 0.f, 0.f);
    if (q < Qn) {
        const float* lg = pc + (size_t)(b * Qn + q) * C1;
        float m = lg[0];
        #pragma unroll
        for (int c = 1; c < C1; c++) m = fmaxf(m, lg[c]);
        float e[C1]; float se = 0.f;
        #pragma unroll
        for (int c = 0; c < C1; c++) { e[c] = __expf(lg[c] - m); se += e[c]; }
        float inv = 1.0f / se;
        #pragma unroll
        for (int c = 0; c < C1; c++) s_negp[c][tid] = -e[c] * inv;
        if (tseg == 0) g_lse[b * Qn + q] = m + logf(se);
        pbq = *reinterpret_cast<const float4*>(pb + (size_t)(b * Qn + q) * 4);
    }
    __syncthreads();
    if (q >= Qn) return;

    float* crow = g_cost + (size_t)b * Tn * Qn + (size_t)t0 * Qn + q;
    #pragma unroll 8
    for (int t = 0; t < TCH; t++) {
        float4 tb4 = s_tb4[t];
        float cc = s_negp[s_lab[t]][tid];
        float cb = fabsf(pbq.x - tb4.x) + fabsf(pbq.y - tb4.y)
                 + fabsf(pbq.z - tb4.z) + fabsf(pbq.w - tb4.w);
        crow[(size_t)t * Qn] = cb + cc;
    }
}

// ============================================================================
// 1b) Row minima of RAW costs: one warp per (image,row).
// ============================================================================
__global__ __launch_bounds__(NT) void rowmin_kernel()
{
    int lane = threadIdx.x & 31;
    int widx = blockIdx.x * (NT / 32) + (threadIdx.x >> 5);   // global row id
    if (widx >= Bn * Tn) return;
    const float* crow = g_cost + (size_t)widx * Qn;

    unsigned long long best = ~0ull;
    #pragma unroll
    for (int s = 0; s < 8; s++) {
        if (s == 7 && lane != 0) break;
        int j0 = (s < 7) ? (s * 128 + lane * 4) : 896;
        float4 c4 = __ldg(reinterpret_cast<const float4*>(crow + j0));
        #pragma unroll
        for (int k = 0; k < 4; k++) {
            unsigned long long e =
                ((unsigned long long)enc_f((&c4.x)[k]) << 32) | (unsigned)(j0 + k + 1);
            if (e < best) best = e;
        }
    }
    #pragma unroll
    for (int s = 16; s; s >>= 1) {
        unsigned long long o = __shfl_down_sync(0xffffffffu, best, s);
        if (o < best) best = o;
    }
    if (lane == 0) {
        g_rowu[widx]   = dec_f((unsigned)(best >> 32));
        g_rowarg[widx] = (int)(best & 0xffffffffu);
    }
}

// ============================================================================
// 2) Hungarian: R14-proven inner loop (unpacked atomic slot) + fused loss
//    with warp-shuffle epilogue reductions (1 barrier instead of 32).
// ============================================================================
__global__ __launch_bounds__(NTH) void hungarian_loss_kernel(
    const float* __restrict__ pc, const float* __restrict__ pb,
    const int* __restrict__ lab, const float* __restrict__ tb,
    float* __restrict__ out)
{
    int b = blockIdx.x;
    int tid = threadIdx.x;
    int lane = tid & 31, warp = tid >> 5;

    __shared__ float u[Tn + 1];
    __shared__ int   way[Qn + 1];
    __shared__ int   p[Qn + 1];
    __shared__ int   rowq[Tn + 1];
    __shared__ unsigned char s_assigned[Tn + 1];
    __shared__ unsigned long long s_gmin[2];   // parity double-buffered argmin
    __shared__ double   sred[4][NWARP];
    __shared__ int      s_last;

    for (int j = tid; j <= Qn; j += NTH) p[j] = 0;
    for (int i = tid; i < Tn; i += NTH) {
        u[i + 1]    = g_rowu[b * Tn + i];
        rowq[i + 1] = g_rowarg[b * Tn + i];
    }
    if (tid == 0) { s_gmin[0] = ~0ull; s_gmin[1] = ~0ull; }
    __syncthreads();

    const float* cost = g_cost + (size_t)b * Tn * Qn;
    const bool valid = (tid < NACT);
    const int  jbase = JPT * tid + 1;     // first owned column (1-based)

    // per-thread column state (owner-private)
    float v4[JPT], minv4[JPT], tu4[JPT];
    unsigned mask = 0;
    #pragma unroll
    for (int k = 0; k < JPT; k++) { v4[k] = 0.f; minv4[k] = FLT_MAX; }

    // ---- greedy assignment (serial, trivial) ----
    if (tid == 0) {
        for (int i = 1; i <= Tn; i++) {
            int j = rowq[i];
            if (p[j] == 0) { p[j] = i; s_assigned[i] = 1; }
            else s_assigned[i] = 0;
        }
    }
    __syncthreads();

    // ---- Dijkstra phases for free rows (deferred duals, register state) ----
    for (int i = 1; i <= Tn; i++) {
        if (s_assigned[i]) continue;
        if (tid == 0) p[0] = i;

        int   i0 = i;
        float C  = 0.f;
        int   lastj1 = 0;
        int   it = 0;
        int   jfinal; float Cf;

        while (true) {
            int par = it & 1;
            float4 cr = make_float4(0.f, 0.f, 0.f, 0.f);
            if (valid) cr = __ldg(reinterpret_cast<const float4*>(
                                  cost + (size_t)(i0 - 1) * Qn + (jbase - 1)));
            float aC = u[i0] - C;

            unsigned benc = 0xFFFFFFFFu; int bj = 0x7FFFFFFF;
            if (valid) {
                #pragma unroll
                for (int k = 0; k < JPT; k++) {
                    if (!(mask & (1u << k))) {
                        float r = (&cr.x)[k] - aC - v4[k];
                        if (r < minv4[k]) { minv4[k] = r; way[jbase + k] = lastj1; }
                        unsigned e = enc_f(minv4[k]);
                        if (e < benc) { benc = e; bj = jbase + k; }
                    }
                }
            }
            unsigned m = __reduce_min_sync(0xffffffffu, benc);
            int cand = (benc == m) ? bj : 0x7FFFFFFF;
            int jm = __reduce_min_sync(0xffffffffu, cand);
            if (lane == 0)
                atomicMin(&s_gmin[par],
                          ((unsigned long long)m << 32) | (unsigned)jm);
            if (tid == 0) s_gmin[par ^ 1] = ~0ull;   // reset next buffer
            __syncthreads();

            unsigned long long g = s_gmin[par];
            unsigned ge = (unsigned)(g >> 32);
            int j1 = (int)(g & 0xFFFFFFFFu);
            float Cn = dec_f(ge);
            int i0n = p[j1];
            if (i0n == 0) { jfinal = j1; Cf = Cn; break; }
            unsigned k1 = (unsigned)(j1 - jbase);
            if (valid && k1 < JPT) { mask |= 1u << k1; tu4[k1] = Cn; }
            lastj1 = j1; C = Cn; i0 = i0n; it++;
        }

        // apply duals (distinct rows per column => race-free) + reset state
        #pragma unroll
        for (int k = 0; k < JPT; k++) {
            if (mask & (1u << k)) {
                float dv = Cf - tu4[k];
                v4[k] -= dv;
                u[p[jbase + k]] += dv;
            }
            minv4[k] = FLT_MAX;
        }
        mask = 0;
        if (tid == 0) { u[i] += Cf; s_gmin[0] = ~0ull; }  // clean buf0 for next phase
        __syncthreads();
        if (tid == 0) {                      // augment along alternating path
            int j0 = jfinal;
            while (j0) { int jp = way[j0]; p[j0] = p[jp]; j0 = jp; }
            s_assigned[i] = 1;
        }
        __syncthreads();
    }

    // ---- build qi per target in shared ----
    for (int j = tid + 1; j <= Qn; j += NTH) {
        int pi = p[j];
        if (pi > 0) rowq[pi] = j - 1;
    }
    __syncthreads();

    // ================= fused per-image loss =================
    int* tcl = way;
    double l1 = 0.0, gsum = 0.0;
    if (tid < Tn) {
        int t = tid;
        int qi = rowq[t + 1];
        const float4 P = *reinterpret_cast<const float4*>(pb + (size_t)(b * Qn + qi) * 4);
        const float4 G = *reinterpret_cast<const float4*>(tb + (size_t)(b * Tn + t) * 4);
        double px = P.x, py = P.y, pw = P.z, ph = P.w;
        double gx = G.x, gy = G.y, gw = G.z, gh = G.w;
        l1 = fabs(px - gx) + fabs(py - gy) + fabs(pw - gw) + fabs(ph - gh);

        double p0 = px - 0.5 * pw, p1 = py - 0.5 * ph, p2 = px + 0.5 * pw, p3 = py + 0.5 * ph;
        double g0 = gx - 0.5 * gw, g1 = gy - 0.5 * gh, g2 = gx + 0.5 * gw, g3 = gy + 0.5 * gh;
        double a1 = (p2 - p0) * (p3 - p1);
        double a2 = (g2 - g0) * (g3 - g1);
        double iw = fmin(p2, g2) - fmax(p0, g0); iw = iw > 0.0 ? iw : 0.0;
        double ih = fmin(p3, g3) - fmax(p1, g1); ih = ih > 0.0 ? ih : 0.0;
        double inter = iw * ih;
        double uni = a1 + a2 - inter;
        double iou = inter / uni;
        double cw = fmax(p2, g2) - fmin(p0, g0);
        double ch = fmax(p3, g3) - fmin(p1, g1);
        double ac = cw * ch;
        double giou = iou - (ac - uni) / ac;
        gsum = 1.0 - giou;
    }

    for (int q = tid; q < Qn; q += NTH) tcl[q] = NUM_CLASSES;
    __syncthreads();
    if (tid < Tn) tcl[rowq[tid + 1]] = lab[b * Tn + tid];
    __syncthreads();

    double wn = 0.0, ws = 0.0;
    for (int q = tid; q < Qn; q += NTH) {
        int c = tcl[q];
        double w = (c == NUM_CLASSES) ? 0.05 : 1.0;
        double nll = (double)g_lse[b * Qn + q] - (double)pc[(size_t)(b * Qn + q) * C1 + c];
        wn += w * nll; ws += w;
    }

    // warp-shuffle reduce all four quantities; 1 barrier total
    #pragma unroll
    for (int s = 16; s; s >>= 1) {
        l1   += __shfl_down_sync(0xffffffffu, l1, s);
        gsum += __shfl_down_sync(0xffffffffu, gsum, s);
        wn   += __shfl_down_sync(0xffffffffu, wn, s);
        ws   += __shfl_down_sync(0xffffffffu, ws, s);
    }
    if (lane == 0) {
        sred[0][warp] = l1; sred[1][warp] = gsum;
        sred[2][warp] = wn; sred[3][warp] = ws;
    }
    __syncthreads();

    if (tid == 0) {
        double l1t = 0.0, gst = 0.0, wnt = 0.0, wst = 0.0;
        #pragma unroll
        for (int w = 0; w < NWARP; w++) {
            l1t += sred[0][w]; gst += sred[1][w];
            wnt += sred[2][w]; wst += sred[3][w];
        }
        double bbox = 5.0 * (l1t / (Tn * 4.0)) + 2.0 * (gst / Tn);
        g_partial[b] = bbox + wnt / wst;
        __threadfence();
        int t = atomicAdd(&g_ctr, 1);
        s_last = (t == Bn - 1);
    }
    __syncthreads();

    if (s_last && warp == 0) {
        double val = ((volatile double*)g_partial)[lane]
                   + ((volatile double*)g_partial)[lane + 32];
        #pragma unroll
        for (int s = 16; s; s >>= 1)
            val += __shfl_down_sync(0xffffffffu, val, s);
        if (lane == 0) {
            out[0] = (float)(val / (double)(Bn * Tn));
            g_ctr = 0;                      // restore for next graph replay
        }
    }
}

extern "C" void kernel_launch(void* const* d_in, const int* in_sizes, int n_in,
                              void* d_out, int out_size)
{
    const float* pc  = (const float*)d_in[0];   // predicted_class [64,900,14]
    const float* pb  = (const float*)d_in[1];   // predicted_bbox  [64,900,4]
    const int*   lab = (const int*)  d_in[2];   // target_labels   [64,128]
    const float* tb  = (const float*)d_in[3];   // target_boxes    [64,128,4]
    float* out = (float*)d_out;

    dim3 cgrid((Qn + NTC - 1) / NTC, Bn, TSPLIT);
    cost_kernel<<<cgrid, NTC>>>(pc, pb, lab, tb);
    rowmin_kernel<<<(Bn * Tn + 7) / 8, NT>>>();
    hungarian_loss_kernel<<<Bn, NTH>>>(pc, pb, lab, tb, out);
}